// round 16
// baseline (speedup 1.0000x reference)
#include <cuda_runtime.h>
#include <cuda_fp16.h>
#include <cstdint>

// B=4, H=16, S=2048, D=64, fp32, causal. Outputs: out [B,H,S,D] then weights [B,H,S,S].
#define SEQ    2048
#define HD     64
#define BM     128            // query rows per CTA (32 per warp, two 16-row slabs)
#define BN     64             // key cols per tile
#define NTHR   128
#define QTILES (SEQ / BM)     // 16
#define KTILES (SEQ / BN)     // 32
#define TILE_SLOTS 512        // uint4 slots per fragment-major 64x64 fp16 tile (8KB)
#define OUT_ELEMS 8388608ull  // 4*16*2048*64

// smem (uint4 units)
#define KS0 0
#define KS1 512
#define VS0 1024
#define VS1 1536
#define SMEM_BYTES_A (1024 * 16)   // 16 KB (K double buffer only)
#define SMEM_BYTES_B (2048 * 16)   // 32 KB

// 1/sqrt(64) * log2(e) folded into Q so softmax is a bare ex2
#define QSCALE 0.18033688011112042f

// Fragment-major fp16 copies of K and V (layouts documented in prep_kv).
__device__ __align__(16) uint4 KH[64 * KTILES * TILE_SLOTS];
__device__ __align__(16) uint4 VH[64 * KTILES * TILE_SLOTS];
// Per-row softmax inverse sums (1/l), produced by sums_kernel.
__device__ float RSbuf[64 * SEQ];

__device__ __forceinline__ uint32_t h2(float lo, float hi) {
    __half2 h = __floats2half2_rn(lo, hi);
    return *reinterpret_cast<uint32_t*>(&h);
}
__device__ __forceinline__ float ex2f(float x) {
    float y;
    asm("ex2.approx.f32 %0, %1;" : "=f"(y) : "f"(x));
    return y;
}
__device__ __forceinline__ void mma16(float c[4],
                                      uint32_t a0, uint32_t a1, uint32_t a2, uint32_t a3,
                                      uint32_t b0, uint32_t b1) {
    asm volatile(
        "mma.sync.aligned.m16n8k16.row.col.f32.f16.f16.f32 "
        "{%0,%1,%2,%3}, {%4,%5,%6,%7}, {%8,%9}, {%0,%1,%2,%3};"
        : "+f"(c[0]), "+f"(c[1]), "+f"(c[2]), "+f"(c[3])
        : "r"(a0), "r"(a1), "r"(a2), "r"(a3), "r"(b0), "r"(b1));
}
__device__ __forceinline__ void cp16(uint32_t dst, const void* src) {
    asm volatile("cp.async.cg.shared.global [%0], [%1], 16;" :: "r"(dst), "l"(src));
}
#define CP_COMMIT() asm volatile("cp.async.commit_group;")
#define CP_WAIT0()  asm volatile("cp.async.wait_group 0;")

// ---------------- Prologue: permute + fp16-round K,V into fragment-major scratch ----------------
__global__ void __launch_bounds__(128)
prep_kv(const float* __restrict__ K, const float* __restrict__ V)
{
    const int jt = blockIdx.x;   // key tile
    const int bh = blockIdx.y;
    const float* Kg = K + ((size_t)bh * SEQ + (size_t)jt * BN) * HD;
    const float* Vg = V + ((size_t)bh * SEQ + (size_t)jt * BN) * HD;
    uint4* Ko = KH + ((size_t)bh * KTILES + jt) * TILE_SLOTS;
    uint4* Vo = VH + ((size_t)bh * KTILES + jt) * TILE_SLOTS;

    #pragma unroll
    for (int i = 0; i < 4; ++i) {
        int s = i * 128 + threadIdx.x;          // slot 0..511
        int lane = s & 31;
        int g = lane >> 2, t = lane & 3;
        // --- K slot: s=(n*2+kkk)*32+lane ---
        {
            int n = s >> 6, kkk = (s >> 5) & 1;
            const float* kr = Kg + (n * 8 + g) * HD + 32 * kkk;
            uint4 o;
            o.x = h2(kr[2*t],        kr[2*t + 1]);
            o.y = h2(kr[2*t + 8],    kr[2*t + 9]);
            o.z = h2(kr[16 + 2*t],   kr[16 + 2*t + 1]);
            o.w = h2(kr[16 + 2*t+8], kr[16 + 2*t + 9]);
            Ko[s] = o;
        }
        // --- V slot: s=(c*4+hh)*32+lane, c in [0,4) 16-key chunk, hh in [0,4) 16-h pair ---
        {
            int c = s >> 7, hh = (s >> 5) & 3;
            const float* vb = Vg + (16 * c) * HD + 16 * hh;
            uint4 o;
            o.x = h2(vb[(2*t)     * HD + g],     vb[(2*t + 1) * HD + g]);
            o.y = h2(vb[(2*t + 8) * HD + g],     vb[(2*t + 9) * HD + g]);
            o.z = h2(vb[(2*t)     * HD + 8 + g], vb[(2*t + 1) * HD + 8 + g]);
            o.w = h2(vb[(2*t + 8) * HD + 8 + g], vb[(2*t + 9) * HD + 8 + g]);
            Vo[s] = o;
        }
    }
}

// Shared helper: load loop-invariant Q fragments (fp16 packed) for a 32-row slab.
__device__ __forceinline__ void load_qa(const float* Qg, int m0, int g, int t,
                                        uint32_t qa[4][8])
{
    const float* Qr0 = Qg + (size_t)(m0 + g) * HD;
    const float* Qr1 = Qg + (size_t)(m0 + g + 8) * HD;
    const float* Qr2 = Qg + (size_t)(m0 + g + 16) * HD;
    const float* Qr3 = Qg + (size_t)(m0 + g + 24) * HD;
    #pragma unroll
    for (int kk = 0; kk < 4; ++kk) {
        int kc = kk * 16;
        qa[kk][0] = h2(Qr0[kc + 2*t]     * QSCALE, Qr0[kc + 2*t + 1] * QSCALE);
        qa[kk][1] = h2(Qr1[kc + 2*t]     * QSCALE, Qr1[kc + 2*t + 1] * QSCALE);
        qa[kk][2] = h2(Qr0[kc + 2*t + 8] * QSCALE, Qr0[kc + 2*t + 9] * QSCALE);
        qa[kk][3] = h2(Qr1[kc + 2*t + 8] * QSCALE, Qr1[kc + 2*t + 9] * QSCALE);
        qa[kk][4] = h2(Qr2[kc + 2*t]     * QSCALE, Qr2[kc + 2*t + 1] * QSCALE);
        qa[kk][5] = h2(Qr3[kc + 2*t]     * QSCALE, Qr3[kc + 2*t + 1] * QSCALE);
        qa[kk][6] = h2(Qr2[kc + 2*t + 8] * QSCALE, Qr2[kc + 2*t + 9] * QSCALE);
        qa[kk][7] = h2(Qr3[kc + 2*t + 8] * QSCALE, Qr3[kc + 2*t + 9] * QSCALE);
    }
}

extern __shared__ uint4 smem4[];

// ================= Kernel A: row sums of exp(scores) -> RSbuf (1/l) =================
__global__ void __launch_bounds__(NTHR, 4)
sums_kernel(const float* __restrict__ Q)
{
    const uint32_t smem_u32 = (uint32_t)__cvta_generic_to_shared(smem4);

    const int qt    = QTILES - 1 - (int)blockIdx.x;
    const int bh    = blockIdx.y;
    const int tid   = threadIdx.x;
    const int warp  = tid >> 5;
    const int lane  = tid & 31;
    const int g     = lane >> 2;
    const int t     = lane & 3;
    const int m0    = warp * 32;
    const int qbase = qt * BM;
    const int jtmax = 2 * qt + 1;

    const float* Qg = Q + (size_t)bh * SEQ * HD + (size_t)qbase * HD;
    const uint4* Kt = KH + (size_t)bh * KTILES * TILE_SLOTS;

    uint32_t qa[4][8];
    load_qa(Qg, m0, g, t, qa);

    auto prefK = [&](int buf, int jt) {
        const uint4* src = Kt + (size_t)jt * TILE_SLOTS;
        uint32_t base = smem_u32 + (uint32_t)(buf ? KS1 : KS0) * 16u;
        #pragma unroll
        for (int i = 0; i < 4; ++i) {
            int s = i * 128 + tid;
            cp16(base + (uint32_t)s * 16u, src + s);
        }
    };

    const int rr0 = qbase + m0 + g;
    const int rr1 = rr0 + 8;
    const int rr2 = rr0 + 16;
    const int rr3 = rr0 + 24;
    const uint32_t FULL = 0xffffffffu;

    float rs0 = 0.f, rs1 = 0.f, rs2 = 0.f, rs3 = 0.f;
    prefK(0, 0); CP_COMMIT();
    for (int jt = 0; jt <= jtmax; ++jt) {
        const int cur = jt & 1;
        CP_WAIT0();
        __syncthreads();
        if (jt < jtmax) { prefK(cur ^ 1, jt + 1); CP_COMMIT(); }
        const uint4* Ks = smem4 + (cur ? KS1 : KS0);
        const bool diag = (jt >= 2 * qt);

        #pragma unroll
        for (int ng = 0; ng < 2; ++ng) {
            float acc[2][4][4];
            #pragma unroll
            for (int s = 0; s < 2; ++s)
                #pragma unroll
                for (int nn = 0; nn < 4; ++nn)
                    acc[s][nn][0] = acc[s][nn][1] = acc[s][nn][2] = acc[s][nn][3] = 0.f;

            #pragma unroll
            for (int kkk = 0; kkk < 2; ++kkk) {
                #pragma unroll
                for (int nn = 0; nn < 4; ++nn) {
                    int n = ng * 4 + nn;
                    uint4 b = Ks[(n * 2 + kkk) * 32 + lane];
                    mma16(acc[0][nn], qa[2*kkk][0],   qa[2*kkk][1],   qa[2*kkk][2],   qa[2*kkk][3],   b.x, b.y);
                    mma16(acc[1][nn], qa[2*kkk][4],   qa[2*kkk][5],   qa[2*kkk][6],   qa[2*kkk][7],   b.x, b.y);
                    mma16(acc[0][nn], qa[2*kkk+1][0], qa[2*kkk+1][1], qa[2*kkk+1][2], qa[2*kkk+1][3], b.z, b.w);
                    mma16(acc[1][nn], qa[2*kkk+1][4], qa[2*kkk+1][5], qa[2*kkk+1][6], qa[2*kkk+1][7], b.z, b.w);
                }
            }

            #pragma unroll
            for (int nn = 0; nn < 4; ++nn) {
                int n = ng * 4 + nn;
                int c0 = jt * BN + n * 8 + 2 * t;
                float p0 = ex2f(acc[0][nn][0]);
                float p1 = ex2f(acc[0][nn][1]);
                float p2 = ex2f(acc[0][nn][2]);
                float p3 = ex2f(acc[0][nn][3]);
                float q0 = ex2f(acc[1][nn][0]);
                float q1 = ex2f(acc[1][nn][1]);
                float q2 = ex2f(acc[1][nn][2]);
                float q3 = ex2f(acc[1][nn][3]);
                if (diag) {
                    if (c0     > rr0) p0 = 0.f;
                    if (c0 + 1 > rr0) p1 = 0.f;
                    if (c0     > rr1) p2 = 0.f;
                    if (c0 + 1 > rr1) p3 = 0.f;
                    if (c0     > rr2) q0 = 0.f;
                    if (c0 + 1 > rr2) q1 = 0.f;
                    if (c0     > rr3) q2 = 0.f;
                    if (c0 + 1 > rr3) q3 = 0.f;
                }
                rs0 += p0 + p1;
                rs1 += p2 + p3;
                rs2 += q0 + q1;
                rs3 += q2 + q3;
            }
        }
    }
    rs0 += __shfl_xor_sync(FULL, rs0, 1); rs0 += __shfl_xor_sync(FULL, rs0, 2);
    rs1 += __shfl_xor_sync(FULL, rs1, 1); rs1 += __shfl_xor_sync(FULL, rs1, 2);
    rs2 += __shfl_xor_sync(FULL, rs2, 1); rs2 += __shfl_xor_sync(FULL, rs2, 2);
    rs3 += __shfl_xor_sync(FULL, rs3, 1); rs3 += __shfl_xor_sync(FULL, rs3, 2);

    if (t == 0) {
        float* rsrow = RSbuf + (size_t)bh * SEQ;
        rsrow[rr0] = 1.f / rs0;
        rsrow[rr1] = 1.f / rs1;
        rsrow[rr2] = 1.f / rs2;
        rsrow[rr3] = 1.f / rs3;
    }
}

// ================= Kernel B: weights + O = P*V (consumes RSbuf) =================
__global__ void __launch_bounds__(NTHR, 3)
attn_kernel(const float* __restrict__ Q, float* __restrict__ Out,
            float* __restrict__ Wts)
{
    const uint32_t smem_u32 = (uint32_t)__cvta_generic_to_shared(smem4);

    const int qt    = QTILES - 1 - (int)blockIdx.x;
    const int bh    = blockIdx.y;
    const int tid   = threadIdx.x;
    const int warp  = tid >> 5;
    const int lane  = tid & 31;
    const int g     = lane >> 2;
    const int t     = lane & 3;
    const int m0    = warp * 32;
    const int qbase = qt * BM;
    const int jtmax = 2 * qt + 1;

    const float* Qg = Q + (size_t)bh * SEQ * HD + (size_t)qbase * HD;
    const uint4* Kt = KH + (size_t)bh * KTILES * TILE_SLOTS;
    const uint4* Vt = VH + (size_t)bh * KTILES * TILE_SLOTS;
    float* Wg = Wts + (size_t)bh * SEQ * SEQ + (size_t)qbase * SEQ;
    float* Og = Out + (size_t)bh * SEQ * HD + (size_t)qbase * HD;

    uint32_t qa[4][8];
    load_qa(Qg, m0, g, t, qa);

    auto prefK = [&](int buf, int jt) {
        const uint4* src = Kt + (size_t)jt * TILE_SLOTS;
        uint32_t base = smem_u32 + (uint32_t)(buf ? KS1 : KS0) * 16u;
        #pragma unroll
        for (int i = 0; i < 4; ++i) {
            int s = i * 128 + tid;
            cp16(base + (uint32_t)s * 16u, src + s);
        }
    };
    auto prefV = [&](int buf, int jt) {
        const uint4* src = Vt + (size_t)jt * TILE_SLOTS;
        uint32_t base = smem_u32 + (uint32_t)(buf ? VS1 : VS0) * 16u;
        #pragma unroll
        for (int i = 0; i < 4; ++i) {
            int s = i * 128 + tid;
            cp16(base + (uint32_t)s * 16u, src + s);
        }
    };

    const int rr0 = qbase + m0 + g;
    const int rr1 = rr0 + 8;
    const int rr2 = rr0 + 16;
    const int rr3 = rr0 + 24;

    const float* rsrow = RSbuf + (size_t)bh * SEQ;
    const float inv0 = rsrow[rr0];
    const float inv1 = rsrow[rr1];
    const float inv2 = rsrow[rr2];
    const float inv3 = rsrow[rr3];

    float accO[2][8][4];
    #pragma unroll
    for (int s = 0; s < 2; ++s)
        #pragma unroll
        for (int n = 0; n < 8; ++n)
            accO[s][n][0] = accO[s][n][1] = accO[s][n][2] = accO[s][n][3] = 0.f;

    prefK(0, 0); prefV(0, 0); CP_COMMIT();
    for (int jt = 0; jt <= jtmax; ++jt) {
        const int cur = jt & 1;
        CP_WAIT0();
        __syncthreads();
        if (jt < jtmax) { prefK(cur ^ 1, jt + 1); prefV(cur ^ 1, jt + 1); CP_COMMIT(); }
        const uint4* Ks = smem4 + (cur ? KS1 : KS0);
        const uint4* Vs = smem4 + (cur ? VS1 : VS0);
        const bool diag = (jt >= 2 * qt);

        #pragma unroll
        for (int ng = 0; ng < 2; ++ng) {
            float acc[2][4][4];
            #pragma unroll
            for (int s = 0; s < 2; ++s)
                #pragma unroll
                for (int nn = 0; nn < 4; ++nn)
                    acc[s][nn][0] = acc[s][nn][1] = acc[s][nn][2] = acc[s][nn][3] = 0.f;

            #pragma unroll
            for (int kkk = 0; kkk < 2; ++kkk) {
                #pragma unroll
                for (int nn = 0; nn < 4; ++nn) {
                    int n = ng * 4 + nn;
                    uint4 b = Ks[(n * 2 + kkk) * 32 + lane];
                    mma16(acc[0][nn], qa[2*kkk][0],   qa[2*kkk][1],   qa[2*kkk][2],   qa[2*kkk][3],   b.x, b.y);
                    mma16(acc[1][nn], qa[2*kkk][4],   qa[2*kkk][5],   qa[2*kkk][6],   qa[2*kkk][7],   b.x, b.y);
                    mma16(acc[0][nn], qa[2*kkk+1][0], qa[2*kkk+1][1], qa[2*kkk+1][2], qa[2*kkk+1][3], b.z, b.w);
                    mma16(acc[1][nn], qa[2*kkk+1][4], qa[2*kkk+1][5], qa[2*kkk+1][6], qa[2*kkk+1][7], b.z, b.w);
                }
            }

            #pragma unroll
            for (int cc = 0; cc < 2; ++cc) {
                int c = 2 * ng + cc;
                float pv[2][2][4];
                #pragma unroll
                for (int sub = 0; sub < 2; ++sub) {
                    int nn = 2 * cc + sub;
                    int n  = ng * 4 + nn;
                    int c0 = jt * BN + n * 8 + 2 * t;
                    float p0 = ex2f(acc[0][nn][0]) * inv0;
                    float p1 = ex2f(acc[0][nn][1]) * inv0;
                    float p2 = ex2f(acc[0][nn][2]) * inv1;
                    float p3 = ex2f(acc[0][nn][3]) * inv1;
                    float q0 = ex2f(acc[1][nn][0]) * inv2;
                    float q1 = ex2f(acc[1][nn][1]) * inv2;
                    float q2 = ex2f(acc[1][nn][2]) * inv3;
                    float q3 = ex2f(acc[1][nn][3]) * inv3;
                    if (diag) {
                        if (c0     > rr0) p0 = 0.f;
                        if (c0 + 1 > rr0) p1 = 0.f;
                        if (c0     > rr1) p2 = 0.f;
                        if (c0 + 1 > rr1) p3 = 0.f;
                        if (c0     > rr2) q0 = 0.f;
                        if (c0 + 1 > rr2) q1 = 0.f;
                        if (c0     > rr3) q2 = 0.f;
                        if (c0 + 1 > rr3) q3 = 0.f;
                    }
                    *(float2*)(Wg + (size_t)(m0 + g)      * SEQ + c0) = make_float2(p0, p1);
                    *(float2*)(Wg + (size_t)(m0 + g + 8)  * SEQ + c0) = make_float2(p2, p3);
                    *(float2*)(Wg + (size_t)(m0 + g + 16) * SEQ + c0) = make_float2(q0, q1);
                    *(float2*)(Wg + (size_t)(m0 + g + 24) * SEQ + c0) = make_float2(q2, q3);
                    pv[sub][0][0] = p0; pv[sub][0][1] = p1; pv[sub][0][2] = p2; pv[sub][0][3] = p3;
                    pv[sub][1][0] = q0; pv[sub][1][1] = q1; pv[sub][1][2] = q2; pv[sub][1][3] = q3;
                }

                uint32_t a00 = h2(pv[0][0][0], pv[0][0][1]);
                uint32_t a01 = h2(pv[0][0][2], pv[0][0][3]);
                uint32_t a02 = h2(pv[1][0][0], pv[1][0][1]);
                uint32_t a03 = h2(pv[1][0][2], pv[1][0][3]);
                uint32_t a10 = h2(pv[0][1][0], pv[0][1][1]);
                uint32_t a11 = h2(pv[0][1][2], pv[0][1][3]);
                uint32_t a12 = h2(pv[1][1][0], pv[1][1][1]);
                uint32_t a13 = h2(pv[1][1][2], pv[1][1][3]);

                #pragma unroll
                for (int hh = 0; hh < 4; ++hh) {
                    uint4 vb = Vs[(c * 4 + hh) * 32 + lane];
                    mma16(accO[0][2*hh],   a00, a01, a02, a03, vb.x, vb.y);
                    mma16(accO[0][2*hh+1], a00, a01, a02, a03, vb.z, vb.w);
                    mma16(accO[1][2*hh],   a10, a11, a12, a13, vb.x, vb.y);
                    mma16(accO[1][2*hh+1], a10, a11, a12, a13, vb.z, vb.w);
                }
            }
        }
    }

    // Zero-fill masked (upper-triangle) weights columns for this 128-row strip (coalesced)
    {
        int zc0   = (qt + 1) * BM;
        int zcols = SEQ - zc0;
        if (zcols > 0) {
            int w4 = zcols >> 2;
            int total4 = BM * w4;
            float4 z = make_float4(0.f, 0.f, 0.f, 0.f);
            for (int idx = tid; idx < total4; idx += NTHR) {
                int r  = idx / w4;
                int c4 = idx - r * w4;
                *(float4*)(Wg + (size_t)r * SEQ + zc0 + c4 * 4) = z;
            }
        }
    }

    // Write O (normalized: P carried 1/l)
    #pragma unroll
    for (int h = 0; h < 8; ++h) {
        int cb = h * 8 + 2 * t;
        *(float2*)(Og + (size_t)(m0 + g)      * HD + cb) = make_float2(accO[0][h][0], accO[0][h][1]);
        *(float2*)(Og + (size_t)(m0 + g + 8)  * HD + cb) = make_float2(accO[0][h][2], accO[0][h][3]);
        *(float2*)(Og + (size_t)(m0 + g + 16) * HD + cb) = make_float2(accO[1][h][0], accO[1][h][1]);
        *(float2*)(Og + (size_t)(m0 + g + 24) * HD + cb) = make_float2(accO[1][h][2], accO[1][h][3]);
    }
}

extern "C" void kernel_launch(void* const* d_in, const int* in_sizes, int n_in,
                              void* d_out, int out_size)
{
    const float* Q = (const float*)d_in[0];
    const float* K = (const float*)d_in[1];
    const float* V = (const float*)d_in[2];
    // d_in[3] = mask; always causal tril for this problem -> handled analytically.
    float* out = (float*)d_out;
    float* wts = out + OUT_ELEMS;

    // 1) Prologue: permute + fp16-round K,V into fragment-major scratch
    dim3 pgrid(KTILES, 64);
    prep_kv<<<pgrid, 128>>>(K, V);

    // 2) Row sums (1/l) -> RSbuf
    cudaFuncSetAttribute(sums_kernel, cudaFuncAttributeMaxDynamicSharedMemorySize, SMEM_BYTES_A);
    dim3 grid(QTILES, 64);
    sums_kernel<<<grid, NTHR, SMEM_BYTES_A>>>(Q);

    // 3) Weights + O
    cudaFuncSetAttribute(attn_kernel, cudaFuncAttributeMaxDynamicSharedMemorySize, SMEM_BYTES_B);
    attn_kernel<<<grid, NTHR, SMEM_BYTES_B>>>(Q, out, wts);
}

// round 17
// speedup vs baseline: 1.1014x; 1.1014x over previous
#include <cuda_runtime.h>
#include <cuda_fp16.h>
#include <cstdint>

// B=4, H=16, S=2048, D=64, fp32, causal. Outputs: out [B,H,S,D] then weights [B,H,S,S].
#define SEQ    2048
#define HD     64
#define BM     128            // query rows per CTA (32 per warp, two 16-row slabs)
#define BN     64             // key cols per tile
#define NTHR   128
#define QTILES (SEQ / BM)     // 16
#define KTILES (SEQ / BN)     // 32
#define TILE_SLOTS 512        // uint4 slots per fragment-major 64x64 fp16 tile (8KB)
#define OUT_ELEMS 8388608ull  // 4*16*2048*64

// smem (uint4 units): double-buffered K then double-buffered V
#define KS0 0
#define KS1 512
#define VS0 1024
#define VS1 1536
#define SMEM_BYTES (2048 * 16)   // 32 KB

// 1/sqrt(64) * log2(e) folded into Q so softmax is a bare ex2
#define QSCALE 0.18033688011112042f

// Fragment-major fp16 copies of K and V (layouts documented in prep_kv).
__device__ __align__(16) uint4 KH[64 * KTILES * TILE_SLOTS];
__device__ __align__(16) uint4 VH[64 * KTILES * TILE_SLOTS];

__device__ __forceinline__ uint32_t h2(float lo, float hi) {
    __half2 h = __floats2half2_rn(lo, hi);
    return *reinterpret_cast<uint32_t*>(&h);
}
__device__ __forceinline__ float ex2f(float x) {
    float y;
    asm("ex2.approx.f32 %0, %1;" : "=f"(y) : "f"(x));
    return y;
}
__device__ __forceinline__ void mma16(float c[4],
                                      uint32_t a0, uint32_t a1, uint32_t a2, uint32_t a3,
                                      uint32_t b0, uint32_t b1) {
    asm volatile(
        "mma.sync.aligned.m16n8k16.row.col.f32.f16.f16.f32 "
        "{%0,%1,%2,%3}, {%4,%5,%6,%7}, {%8,%9}, {%0,%1,%2,%3};"
        : "+f"(c[0]), "+f"(c[1]), "+f"(c[2]), "+f"(c[3])
        : "r"(a0), "r"(a1), "r"(a2), "r"(a3), "r"(b0), "r"(b1));
}
__device__ __forceinline__ void cp16(uint32_t dst, const void* src) {
    asm volatile("cp.async.cg.shared.global [%0], [%1], 16;" :: "r"(dst), "l"(src));
}
#define CP_COMMIT() asm volatile("cp.async.commit_group;")
#define CP_WAIT0()  asm volatile("cp.async.wait_group 0;")

// ---------------- Prologue: permute + fp16-round K,V into fragment-major scratch ----------------
__global__ void __launch_bounds__(128)
prep_kv(const float* __restrict__ K, const float* __restrict__ V)
{
    const int jt = blockIdx.x;   // key tile
    const int bh = blockIdx.y;
    const float* Kg = K + ((size_t)bh * SEQ + (size_t)jt * BN) * HD;
    const float* Vg = V + ((size_t)bh * SEQ + (size_t)jt * BN) * HD;
    uint4* Ko = KH + ((size_t)bh * KTILES + jt) * TILE_SLOTS;
    uint4* Vo = VH + ((size_t)bh * KTILES + jt) * TILE_SLOTS;

    #pragma unroll
    for (int i = 0; i < 4; ++i) {
        int s = i * 128 + threadIdx.x;          // slot 0..511
        int lane = s & 31;
        int g = lane >> 2, t = lane & 3;
        // --- K slot: s=(n*2+kkk)*32+lane ---
        {
            int n = s >> 6, kkk = (s >> 5) & 1;
            const float* kr = Kg + (n * 8 + g) * HD + 32 * kkk;
            uint4 o;
            o.x = h2(kr[2*t],        kr[2*t + 1]);
            o.y = h2(kr[2*t + 8],    kr[2*t + 9]);
            o.z = h2(kr[16 + 2*t],   kr[16 + 2*t + 1]);
            o.w = h2(kr[16 + 2*t+8], kr[16 + 2*t + 9]);
            Ko[s] = o;
        }
        // --- V slot: s=(c*4+hh)*32+lane, c in [0,4) 16-key chunk, hh in [0,4) 16-h pair ---
        {
            int c = s >> 7, hh = (s >> 5) & 3;
            const float* vb = Vg + (16 * c) * HD + 16 * hh;
            uint4 o;
            o.x = h2(vb[(2*t)     * HD + g],     vb[(2*t + 1) * HD + g]);
            o.y = h2(vb[(2*t + 8) * HD + g],     vb[(2*t + 9) * HD + g]);
            o.z = h2(vb[(2*t)     * HD + 8 + g], vb[(2*t + 1) * HD + 8 + g]);
            o.w = h2(vb[(2*t + 8) * HD + 8 + g], vb[(2*t + 9) * HD + 8 + g]);
            Vo[s] = o;
        }
    }
}

extern __shared__ uint4 smem4[];

__global__ void __launch_bounds__(NTHR, 3)
attn_kernel(const float* __restrict__ Q, float* __restrict__ Out,
            float* __restrict__ Wts)
{
    const uint32_t smem_u32 = (uint32_t)__cvta_generic_to_shared(smem4);

    const int qt    = QTILES - 1 - (int)blockIdx.x;   // heavy tiles first
    const int bh    = blockIdx.y;
    const int tid   = threadIdx.x;
    const int warp  = tid >> 5;
    const int lane  = tid & 31;
    const int g     = lane >> 2;       // 0..7
    const int t     = lane & 3;        // 0..3
    const int m0    = warp * 32;       // warp's 32-row slab base within tile
    const int qbase = qt * BM;
    const int jtmax = 2 * qt + 1;

    const float* Qg = Q + (size_t)bh * SEQ * HD + (size_t)qbase * HD;
    const uint4* Kt = KH + (size_t)bh * KTILES * TILE_SLOTS;
    const uint4* Vt = VH + (size_t)bh * KTILES * TILE_SLOTS;
    float* Wg = Wts + (size_t)bh * SEQ * SEQ + (size_t)qbase * SEQ;
    float* Og = Out + (size_t)bh * SEQ * HD + (size_t)qbase * HD;

    // ---- Hoisted Q fragments (loop-invariant fp16): 4 k-chunks x 8 packed regs ----
    uint32_t qa[4][8];
    {
        const float* Qr0 = Qg + (size_t)(m0 + g) * HD;
        const float* Qr1 = Qg + (size_t)(m0 + g + 8) * HD;
        const float* Qr2 = Qg + (size_t)(m0 + g + 16) * HD;
        const float* Qr3 = Qg + (size_t)(m0 + g + 24) * HD;
        #pragma unroll
        for (int kk = 0; kk < 4; ++kk) {
            int kc = kk * 16;
            qa[kk][0] = h2(Qr0[kc + 2*t]     * QSCALE, Qr0[kc + 2*t + 1] * QSCALE);
            qa[kk][1] = h2(Qr1[kc + 2*t]     * QSCALE, Qr1[kc + 2*t + 1] * QSCALE);
            qa[kk][2] = h2(Qr0[kc + 2*t + 8] * QSCALE, Qr0[kc + 2*t + 9] * QSCALE);
            qa[kk][3] = h2(Qr1[kc + 2*t + 8] * QSCALE, Qr1[kc + 2*t + 9] * QSCALE);
            qa[kk][4] = h2(Qr2[kc + 2*t]     * QSCALE, Qr2[kc + 2*t + 1] * QSCALE);
            qa[kk][5] = h2(Qr3[kc + 2*t]     * QSCALE, Qr3[kc + 2*t + 1] * QSCALE);
            qa[kk][6] = h2(Qr2[kc + 2*t + 8] * QSCALE, Qr2[kc + 2*t + 9] * QSCALE);
            qa[kk][7] = h2(Qr3[kc + 2*t + 8] * QSCALE, Qr3[kc + 2*t + 9] * QSCALE);
        }
    }

    // prefetchers: contiguous 8KB tile copy, 4 x 16B per thread
    auto prefK = [&](int buf, int jt) {
        const uint4* src = Kt + (size_t)jt * TILE_SLOTS;
        uint32_t base = smem_u32 + (uint32_t)(buf ? KS1 : KS0) * 16u;
        #pragma unroll
        for (int i = 0; i < 4; ++i) {
            int s = i * 128 + tid;
            cp16(base + (uint32_t)s * 16u, src + s);
        }
    };
    auto prefV = [&](int buf, int jt) {
        const uint4* src = Vt + (size_t)jt * TILE_SLOTS;
        uint32_t base = smem_u32 + (uint32_t)(buf ? VS1 : VS0) * 16u;
        #pragma unroll
        for (int i = 0; i < 4; ++i) {
            int s = i * 128 + tid;
            cp16(base + (uint32_t)s * 16u, src + s);
        }
    };

    const int rr0 = qbase + m0 + g;
    const int rr1 = rr0 + 8;
    const int rr2 = rr0 + 16;
    const int rr3 = rr0 + 24;
    const uint32_t FULL = 0xffffffffu;

    // ================= Phase A: row sums of exp(scores) =================
    // Single barrier per iter: wait -> sync -> prefetch(jt+1) -> compute(jt).
    float rs0 = 0.f, rs1 = 0.f, rs2 = 0.f, rs3 = 0.f;
    prefK(0, 0); CP_COMMIT();
    for (int jt = 0; jt <= jtmax; ++jt) {
        const int cur = jt & 1;
        CP_WAIT0();
        __syncthreads();
        if (jt < jtmax) { prefK(cur ^ 1, jt + 1); CP_COMMIT(); }
        const uint4* Ks = smem4 + (cur ? KS1 : KS0);
        const bool diag = (jt >= 2 * qt);

        #pragma unroll
        for (int ng = 0; ng < 2; ++ng) {
            float acc[2][4][4];
            #pragma unroll
            for (int s = 0; s < 2; ++s)
                #pragma unroll
                for (int nn = 0; nn < 4; ++nn)
                    acc[s][nn][0] = acc[s][nn][1] = acc[s][nn][2] = acc[s][nn][3] = 0.f;

            #pragma unroll
            for (int kkk = 0; kkk < 2; ++kkk) {
                #pragma unroll
                for (int nn = 0; nn < 4; ++nn) {
                    int n = ng * 4 + nn;
                    uint4 b = Ks[(n * 2 + kkk) * 32 + lane];
                    mma16(acc[0][nn], qa[2*kkk][0],   qa[2*kkk][1],   qa[2*kkk][2],   qa[2*kkk][3],   b.x, b.y);
                    mma16(acc[1][nn], qa[2*kkk][4],   qa[2*kkk][5],   qa[2*kkk][6],   qa[2*kkk][7],   b.x, b.y);
                    mma16(acc[0][nn], qa[2*kkk+1][0], qa[2*kkk+1][1], qa[2*kkk+1][2], qa[2*kkk+1][3], b.z, b.w);
                    mma16(acc[1][nn], qa[2*kkk+1][4], qa[2*kkk+1][5], qa[2*kkk+1][6], qa[2*kkk+1][7], b.z, b.w);
                }
            }

            #pragma unroll
            for (int nn = 0; nn < 4; ++nn) {
                int n = ng * 4 + nn;
                int c0 = jt * BN + n * 8 + 2 * t;
                float p0 = ex2f(acc[0][nn][0]);
                float p1 = ex2f(acc[0][nn][1]);
                float p2 = ex2f(acc[0][nn][2]);
                float p3 = ex2f(acc[0][nn][3]);
                float q0 = ex2f(acc[1][nn][0]);
                float q1 = ex2f(acc[1][nn][1]);
                float q2 = ex2f(acc[1][nn][2]);
                float q3 = ex2f(acc[1][nn][3]);
                if (diag) {
                    if (c0     > rr0) p0 = 0.f;
                    if (c0 + 1 > rr0) p1 = 0.f;
                    if (c0     > rr1) p2 = 0.f;
                    if (c0 + 1 > rr1) p3 = 0.f;
                    if (c0     > rr2) q0 = 0.f;
                    if (c0 + 1 > rr2) q1 = 0.f;
                    if (c0     > rr3) q2 = 0.f;
                    if (c0 + 1 > rr3) q3 = 0.f;
                }
                rs0 += p0 + p1;
                rs1 += p2 + p3;
                rs2 += q0 + q1;
                rs3 += q2 + q3;
            }
        }
    }
    rs0 += __shfl_xor_sync(FULL, rs0, 1); rs0 += __shfl_xor_sync(FULL, rs0, 2);
    rs1 += __shfl_xor_sync(FULL, rs1, 1); rs1 += __shfl_xor_sync(FULL, rs1, 2);
    rs2 += __shfl_xor_sync(FULL, rs2, 1); rs2 += __shfl_xor_sync(FULL, rs2, 2);
    rs3 += __shfl_xor_sync(FULL, rs3, 1); rs3 += __shfl_xor_sync(FULL, rs3, 2);
    const float inv0 = 1.f / rs0;
    const float inv1 = 1.f / rs1;
    const float inv2 = 1.f / rs2;
    const float inv3 = 1.f / rs3;

    // ================= Phase B: weights + O = P*V =================
    float accO[2][8][4];
    #pragma unroll
    for (int s = 0; s < 2; ++s)
        #pragma unroll
        for (int n = 0; n < 8; ++n)
            accO[s][n][0] = accO[s][n][1] = accO[s][n][2] = accO[s][n][3] = 0.f;

    prefK(0, 0); prefV(0, 0); CP_COMMIT();
    for (int jt = 0; jt <= jtmax; ++jt) {
        const int cur = jt & 1;
        CP_WAIT0();
        __syncthreads();
        if (jt < jtmax) { prefK(cur ^ 1, jt + 1); prefV(cur ^ 1, jt + 1); CP_COMMIT(); }
        const uint4* Ks = smem4 + (cur ? KS1 : KS0);
        const uint4* Vs = smem4 + (cur ? VS1 : VS0);
        const bool diag = (jt >= 2 * qt);

        #pragma unroll
        for (int ng = 0; ng < 2; ++ng) {
            float acc[2][4][4];
            #pragma unroll
            for (int s = 0; s < 2; ++s)
                #pragma unroll
                for (int nn = 0; nn < 4; ++nn)
                    acc[s][nn][0] = acc[s][nn][1] = acc[s][nn][2] = acc[s][nn][3] = 0.f;

            #pragma unroll
            for (int kkk = 0; kkk < 2; ++kkk) {
                #pragma unroll
                for (int nn = 0; nn < 4; ++nn) {
                    int n = ng * 4 + nn;
                    uint4 b = Ks[(n * 2 + kkk) * 32 + lane];
                    mma16(acc[0][nn], qa[2*kkk][0],   qa[2*kkk][1],   qa[2*kkk][2],   qa[2*kkk][3],   b.x, b.y);
                    mma16(acc[1][nn], qa[2*kkk][4],   qa[2*kkk][5],   qa[2*kkk][6],   qa[2*kkk][7],   b.x, b.y);
                    mma16(acc[0][nn], qa[2*kkk+1][0], qa[2*kkk+1][1], qa[2*kkk+1][2], qa[2*kkk+1][3], b.z, b.w);
                    mma16(acc[1][nn], qa[2*kkk+1][4], qa[2*kkk+1][5], qa[2*kkk+1][6], qa[2*kkk+1][7], b.z, b.w);
                }
            }

            #pragma unroll
            for (int cc = 0; cc < 2; ++cc) {
                int c = 2 * ng + cc;               // 16-key chunk index within tile
                float pv[2][2][4];                 // [sub-tile][slab][elem]
                #pragma unroll
                for (int sub = 0; sub < 2; ++sub) {
                    int nn = 2 * cc + sub;
                    int n  = ng * 4 + nn;
                    int c0 = jt * BN + n * 8 + 2 * t;
                    float p0 = ex2f(acc[0][nn][0]) * inv0;
                    float p1 = ex2f(acc[0][nn][1]) * inv0;
                    float p2 = ex2f(acc[0][nn][2]) * inv1;
                    float p3 = ex2f(acc[0][nn][3]) * inv1;
                    float q0 = ex2f(acc[1][nn][0]) * inv2;
                    float q1 = ex2f(acc[1][nn][1]) * inv2;
                    float q2 = ex2f(acc[1][nn][2]) * inv3;
                    float q3 = ex2f(acc[1][nn][3]) * inv3;
                    if (diag) {
                        if (c0     > rr0) p0 = 0.f;
                        if (c0 + 1 > rr0) p1 = 0.f;
                        if (c0     > rr1) p2 = 0.f;
                        if (c0 + 1 > rr1) p3 = 0.f;
                        if (c0     > rr2) q0 = 0.f;
                        if (c0 + 1 > rr2) q1 = 0.f;
                        if (c0     > rr3) q2 = 0.f;
                        if (c0 + 1 > rr3) q3 = 0.f;
                    }
                    // normalized weights -> gmem (fp32, streaming/evict-first)
                    __stcs((float2*)(Wg + (size_t)(m0 + g)      * SEQ + c0), make_float2(p0, p1));
                    __stcs((float2*)(Wg + (size_t)(m0 + g + 8)  * SEQ + c0), make_float2(p2, p3));
                    __stcs((float2*)(Wg + (size_t)(m0 + g + 16) * SEQ + c0), make_float2(q0, q1));
                    __stcs((float2*)(Wg + (size_t)(m0 + g + 24) * SEQ + c0), make_float2(q2, q3));
                    pv[sub][0][0] = p0; pv[sub][0][1] = p1; pv[sub][0][2] = p2; pv[sub][0][3] = p3;
                    pv[sub][1][0] = q0; pv[sub][1][1] = q1; pv[sub][1][2] = q2; pv[sub][1][3] = q3;
                }

                // Pack P into fp16 A-fragments for this 16-key chunk (no permutation needed)
                uint32_t a00 = h2(pv[0][0][0], pv[0][0][1]);
                uint32_t a01 = h2(pv[0][0][2], pv[0][0][3]);
                uint32_t a02 = h2(pv[1][0][0], pv[1][0][1]);
                uint32_t a03 = h2(pv[1][0][2], pv[1][0][3]);
                uint32_t a10 = h2(pv[0][1][0], pv[0][1][1]);
                uint32_t a11 = h2(pv[0][1][2], pv[0][1][3]);
                uint32_t a12 = h2(pv[1][1][0], pv[1][1][1]);
                uint32_t a13 = h2(pv[1][1][2], pv[1][1][3]);

                #pragma unroll
                for (int hh = 0; hh < 4; ++hh) {
                    uint4 vb = Vs[(c * 4 + hh) * 32 + lane];
                    mma16(accO[0][2*hh],   a00, a01, a02, a03, vb.x, vb.y);
                    mma16(accO[0][2*hh+1], a00, a01, a02, a03, vb.z, vb.w);
                    mma16(accO[1][2*hh],   a10, a11, a12, a13, vb.x, vb.y);
                    mma16(accO[1][2*hh+1], a10, a11, a12, a13, vb.z, vb.w);
                }
            }
        }
    }

    // Write O (normalized: P carried 1/l)
    #pragma unroll
    for (int h = 0; h < 8; ++h) {
        int cb = h * 8 + 2 * t;
        __stcs((float2*)(Og + (size_t)(m0 + g)      * HD + cb), make_float2(accO[0][h][0], accO[0][h][1]));
        __stcs((float2*)(Og + (size_t)(m0 + g + 8)  * HD + cb), make_float2(accO[0][h][2], accO[0][h][3]));
        __stcs((float2*)(Og + (size_t)(m0 + g + 16) * HD + cb), make_float2(accO[1][h][0], accO[1][h][1]));
        __stcs((float2*)(Og + (size_t)(m0 + g + 24) * HD + cb), make_float2(accO[1][h][2], accO[1][h][3]));
    }

    // Zero-fill masked (upper-triangle) weights columns for this 128-row strip
    // (coalesced: consecutive tid -> consecutive float4; streaming stores)
    {
        int zc0   = (qt + 1) * BM;
        int zcols = SEQ - zc0;
        if (zcols > 0) {
            int w4 = zcols >> 2;
            int total4 = BM * w4;
            float4 z = make_float4(0.f, 0.f, 0.f, 0.f);
            for (int idx = tid; idx < total4; idx += NTHR) {
                int r  = idx / w4;
                int c4 = idx - r * w4;
                __stcs((float4*)(Wg + (size_t)r * SEQ + zc0) + c4, z);
            }
        }
    }
}

extern "C" void kernel_launch(void* const* d_in, const int* in_sizes, int n_in,
                              void* d_out, int out_size)
{
    const float* Q = (const float*)d_in[0];
    const float* K = (const float*)d_in[1];
    const float* V = (const float*)d_in[2];
    // d_in[3] = mask; always causal tril for this problem -> handled analytically.
    float* out = (float*)d_out;
    float* wts = out + OUT_ELEMS;

    // Prologue: permute + fp16-round K,V into fragment-major scratch (same stream -> ordered)
    dim3 pgrid(KTILES, 64);
    prep_kv<<<pgrid, 128>>>(K, V);

    cudaFuncSetAttribute(attn_kernel, cudaFuncAttributeMaxDynamicSharedMemorySize, SMEM_BYTES);

    dim3 grid(QTILES, 64);  // (16 q-tiles, B*H)
    attn_kernel<<<grid, NTHR, SMEM_BYTES>>>(Q, out, wts);
}